// round 4
// baseline (speedup 1.0000x reference)
#include <cuda_runtime.h>
#include <math.h>

#define S_TOT 2304
#define S0    2048
#define DIM   1536
#define NH    24
#define HD    64
#define QKV_N 4608

// ---------------- scratch (device globals; no allocation allowed) -----------
__device__ float g_q[NH * S_TOT * HD];      // raw -> normed+roped in place
__device__ float g_k[NH * S_TOT * HD];
__device__ float g_v[NH * S_TOT * HD];
__device__ float g_attn[S_TOT * DIM];       // attention out, (S, h*d) layout

// ---------------- tiled fp32 GEMM: 128x128 block, 8x8 microtile -------------
// MODE 0: QKV projection. A = x0/x1 by row band, B = w_qkv0/1.
//         Epilogue scatters columns (t,h,d) into g_q/g_k/g_v [h][S][d].
// MODE 1: output projection. A = g_attn, B = w_out0/1 by row band.
//         Epilogue writes d_out[s*1536 + n].
template <int MODE>
__global__ __launch_bounds__(256) void gemm128(
    const float* __restrict__ A0, const float* __restrict__ A1,
    const float* __restrict__ B0, const float* __restrict__ B1,
    float* __restrict__ out, int ldb)
{
    __shared__ float As[16][128];
    __shared__ float Bs[16][128];

    const int bx = blockIdx.x, by = blockIdx.y;
    const int tid = threadIdx.x;
    const int m0 = by * 128;
    const int n0 = bx * 128;

    const float* A;
    const float* B;
    if (MODE == 0) {
        if (m0 < S0) { A = A0 + (size_t)m0 * DIM;        B = B0; }
        else         { A = A1 + (size_t)(m0 - S0) * DIM; B = B1; }
    } else {
        A = g_attn + (size_t)m0 * DIM;
        B = (m0 < S0) ? B0 : B1;
    }
    B += n0;

    const int tx = tid & 15;
    const int ty = tid >> 4;

    float acc[8][8];
#pragma unroll
    for (int i = 0; i < 8; i++)
#pragma unroll
        for (int j = 0; j < 8; j++) acc[i][j] = 0.0f;

    const int arow = tid >> 2;          // 0..63
    const int acol = (tid & 3) << 2;    // 0,4,8,12
    const int brow = tid >> 5;          // 0..7
    const int bcol = (tid & 31) << 2;   // 0..124

    for (int k0 = 0; k0 < DIM; k0 += 16) {
#pragma unroll
        for (int i = 0; i < 2; i++) {
            int r = arow + i * 64;
            float4 v = *(const float4*)(A + (size_t)r * DIM + k0 + acol);
            As[acol + 0][r] = v.x;
            As[acol + 1][r] = v.y;
            As[acol + 2][r] = v.z;
            As[acol + 3][r] = v.w;
        }
#pragma unroll
        for (int i = 0; i < 2; i++) {
            int r = brow + i * 8;
            *(float4*)&Bs[r][bcol] =
                *(const float4*)(B + (size_t)(k0 + r) * ldb + bcol);
        }
        __syncthreads();

#pragma unroll
        for (int k = 0; k < 16; k++) {
            float ra[8], rb[8];
#pragma unroll
            for (int i = 0; i < 4; i++) {
                float4 v = *(const float4*)&As[k][ty * 8 + i * 4];
                ra[i * 4 + 0] = v.x; ra[i * 4 + 1] = v.y;
                ra[i * 4 + 2] = v.z; ra[i * 4 + 3] = v.w;
            }
#pragma unroll
            for (int j = 0; j < 4; j++) {
                float4 v = *(const float4*)&Bs[k][tx * 8 + j * 4];
                rb[j * 4 + 0] = v.x; rb[j * 4 + 1] = v.y;
                rb[j * 4 + 2] = v.z; rb[j * 4 + 3] = v.w;
            }
            // wait... keep straightforward: overwrite with scalar indexing
#pragma unroll
            for (int i = 0; i < 8; i++)
#pragma unroll
                for (int j = 0; j < 8; j++)
                    acc[i][j] += ra[i] * rb[j];
        }
        __syncthreads();
    }

    if (MODE == 0) {
#pragma unroll
        for (int i = 0; i < 8; i++) {
            int m = m0 + ty * 8 + i;
#pragma unroll
            for (int j = 0; j < 8; j++) {
                int c = n0 + tx * 8 + j;
                int t = c / DIM;
                int rem = c - t * DIM;
                int h = rem >> 6;
                int d = rem & 63;
                float* dst = (t == 0) ? g_q : (t == 1) ? g_k : g_v;
                dst[((size_t)h * S_TOT + m) * HD + d] = acc[i][j];
            }
        }
    } else {
#pragma unroll
        for (int i = 0; i < 8; i++) {
            int m = m0 + ty * 8 + i;
#pragma unroll
            for (int j = 0; j < 8; j += 4) {
                float4 v = make_float4(acc[i][j], acc[i][j + 1],
                                       acc[i][j + 2], acc[i][j + 3]);
                *(float4*)&out[(size_t)m * DIM + n0 + tx * 8 + j] = v;
            }
        }
    }
}

// ---------------- RMSNorm + RoPE, one warp per (h, s) row -------------------
__global__ __launch_bounds__(256) void norm_rope_kernel(
    const float* __restrict__ gq0, const float* __restrict__ gk0,
    const float* __restrict__ gq1, const float* __restrict__ gk1)
{
    const int warp = (blockIdx.x * blockDim.x + threadIdx.x) >> 5;
    const int lane = threadIdx.x & 31;
    if (warp >= NH * S_TOT) return;
    const int h = warp / S_TOT;
    const int s = warp - h * S_TOT;

    const float* gq;
    const float* gk;
    int pos;
    if (s < S0) { gq = gq0; gk = gk0; pos = s; }
    else        { gq = gq1; gk = gk1; pos = s - S0; }

    // inv freq in double once (angle error << 1e-4 even at pos ~2047)
    const double LN1E4_OVER_32 = 0.2878231217852968;  // ln(10000)/32
    float inv = (float)exp(-(double)lane * LN1E4_OVER_32);
    float f = (float)pos * inv;
    float cs, sn;
    sincosf(f, &sn, &cs);

    const size_t base = ((size_t)h * S_TOT + s) * HD;
    const float gql = gq[lane], gqh = gq[lane + 32];
    const float gkl = gk[lane], gkh = gk[lane + 32];

    // ---- Q ----
    {
        float lo = g_q[base + lane];
        float hi = g_q[base + lane + 32];
        float ss = lo * lo + hi * hi;
#pragma unroll
        for (int off = 16; off; off >>= 1)
            ss += __shfl_xor_sync(0xffffffffu, ss, off);
        float r = rsqrtf(ss * (1.0f / 64.0f) + 1e-6f);
        float nl = lo * r * gql;
        float nh = hi * r * gqh;
        g_q[base + lane]      = nl * cs - nh * sn;
        g_q[base + lane + 32] = nh * cs + nl * sn;
    }
    // ---- K ----
    {
        float lo = g_k[base + lane];
        float hi = g_k[base + lane + 32];
        float ss = lo * lo + hi * hi;
#pragma unroll
        for (int off = 16; off; off >>= 1)
            ss += __shfl_xor_sync(0xffffffffu, ss, off);
        float r = rsqrtf(ss * (1.0f / 64.0f) + 1e-6f);
        float nl = lo * r * gkl;
        float nh = hi * r * gkh;
        g_k[base + lane]      = nl * cs - nh * sn;
        g_k[base + lane + 32] = nh * cs + nl * sn;
    }
}

// ---------------- attention: 1 query row per thread, online softmax ---------
// grid (S/128, NH), 128 threads. K/V tiles of 32 rows staged in smem; inner
// dot products read K/V rows via broadcast float4 LDS against register q/o.
__global__ __launch_bounds__(128) void attn_kernel()
{
    const int h = blockIdx.y;
    const int qi = blockIdx.x * 128 + threadIdx.x;

    __shared__ float Ks[32 * 64];
    __shared__ float Vs[32 * 64];

    float q[64];
    {
        const float* qptr = g_q + ((size_t)h * S_TOT + qi) * HD;
#pragma unroll
        for (int i = 0; i < 16; i++) {
            float4 v = *(const float4*)(qptr + i * 4);
            q[i * 4 + 0] = v.x; q[i * 4 + 1] = v.y;
            q[i * 4 + 2] = v.z; q[i * 4 + 3] = v.w;
        }
    }

    float o[64];
#pragma unroll
    for (int i = 0; i < 64; i++) o[i] = 0.0f;
    float m = -1e30f, l = 0.0f;

    const float* kbase = g_k + (size_t)h * S_TOT * HD;
    const float* vbase = g_v + (size_t)h * S_TOT * HD;
    const float scale = 0.125f;  // 1/sqrt(64)

    for (int kt = 0; kt < S_TOT; kt += 32) {
        __syncthreads();
#pragma unroll
        for (int i = 0; i < 4; i++) {
            int off = i * 512 + threadIdx.x * 4;
            *(float4*)&Ks[off] = *(const float4*)(kbase + (size_t)kt * HD + off);
            *(float4*)&Vs[off] = *(const float4*)(vbase + (size_t)kt * HD + off);
        }
        __syncthreads();

#pragma unroll
        for (int half = 0; half < 2; half++) {
            float sv[16];
#pragma unroll
            for (int kk = 0; kk < 16; kk++) {
                const float* kr = &Ks[(half * 16 + kk) * 64];
                float d0 = 0.f, d1 = 0.f, d2 = 0.f, d3 = 0.f;
#pragma unroll
                for (int i = 0; i < 16; i++) {
                    float4 kv = *(const float4*)(kr + i * 4);
                    d0 += q[i * 4 + 0] * kv.x;
                    d1 += q[i * 4 + 1] * kv.y;
                    d2 += q[i * 4 + 2] * kv.z;
                    d3 += q[i * 4 + 3] * kv.w;
                }
                sv[kk] = ((d0 + d1) + (d2 + d3)) * scale;
            }
            float mt = sv[0];
#pragma unroll
            for (int kk = 1; kk < 16; kk++) mt = fmaxf(mt, sv[kk]);
            float mnew = fmaxf(m, mt);
            float corr = __expf(m - mnew);
            m = mnew;
            l *= corr;
#pragma unroll
            for (int i = 0; i < 64; i++) o[i] *= corr;
#pragma unroll
            for (int kk = 0; kk < 16; kk++) {
                float p = __expf(sv[kk] - m);
                l += p;
                const float* vr = &Vs[(half * 16 + kk) * 64];
#pragma unroll
                for (int i = 0; i < 16; i++) {
                    float4 vv = *(const float4*)(vr + i * 4);
                    o[i * 4 + 0] += p * vv.x;
                    o[i * 4 + 1] += p * vv.y;
                    o[i * 4 + 2] += p * vv.z;
                    o[i * 4 + 3] += p * vv.w;
                }
            }
        }
    }

    const float linv = 1.0f / l;
    float* optr = g_attn + (size_t)qi * DIM + h * HD;
#pragma unroll
    for (int i = 0; i < 16; i++) {
        float4 v = make_float4(o[i * 4 + 0] * linv, o[i * 4 + 1] * linv,
                               o[i * 4 + 2] * linv, o[i * 4 + 3] * linv);
        *(float4*)(optr + i * 4) = v;
    }
}

// ---------------- launch ----------------------------------------------------
extern "C" void kernel_launch(void* const* d_in, const int* in_sizes, int n_in,
                              void* d_out, int out_size)
{
    const float* x0     = (const float*)d_in[0];
    const float* x1     = (const float*)d_in[1];
    const float* w_qkv0 = (const float*)d_in[2];
    const float* w_qkv1 = (const float*)d_in[3];
    const float* w_out0 = (const float*)d_in[4];
    const float* w_out1 = (const float*)d_in[5];
    const float* gq0    = (const float*)d_in[6];
    const float* gk0    = (const float*)d_in[7];
    const float* gq1    = (const float*)d_in[8];
    const float* gk1    = (const float*)d_in[9];
    float* out = (float*)d_out;

    // A: QKV projection (M=2304, N=4608, K=1536) + scatter into q/k/v
    {
        dim3 grid(QKV_N / 128, S_TOT / 128);
        gemm128<0><<<grid, 256>>>(x0, x1, w_qkv0, w_qkv1, nullptr, QKV_N);
    }
    // B: RMSNorm + RoPE on q,k (one warp per (h,s))
    {
        int warps = NH * S_TOT;
        int blocks = (warps * 32 + 255) / 256;
        norm_rope_kernel<<<blocks, 256>>>(gq0, gk0, gq1, gk1);
    }
    // C: attention
    {
        dim3 grid(S_TOT / 128, NH);
        attn_kernel<<<grid, 128>>>();
    }
    // D: output projection (M=2304, N=1536, K=1536), modality-split weights
    {
        dim3 grid(DIM / 128, S_TOT / 128);
        gemm128<1><<<grid, 256>>>(nullptr, nullptr, w_out0, w_out1, out, DIM);
    }
}

// round 7
// speedup vs baseline: 1.2668x; 1.2668x over previous
#include <cuda_runtime.h>
#include <cuda_fp16.h>
#include <math.h>
#include <stdint.h>

#define S_TOT 2304
#define S0    2048
#define DIM   1536
#define NH    24
#define HD    64
#define QKV_N 4608
#define XK    3072          // split-fp16 K layout: [hi 0:1536 | lo 1536:3072]

// GEMM staging
#define N_STAGE 24
#define KCH     64                  // halves per stage
#define PITCH   72                  // halves per smem row (pad 8)
#define TILE_B  (128 * PITCH * 2)   // 18432 B per operand tile
#define STAGE_B (4 * TILE_B)        // Ah, Al, Bh, Bl
#define GEMM_SMEM (2 * STAGE_B)     // 147456 B double-buffered

// ---------------- scratch (device globals; no allocation allowed) -----------
__device__ float  g_q[NH * S_TOT * HD];
__device__ float  g_k[NH * S_TOT * HD];
__device__ float  g_v[NH * S_TOT * HD];
__device__ __half g_xh [S_TOT * XK];          // x (split fp16), K-major
__device__ __half g_ah [S_TOT * XK];          // attention out (split fp16)
__device__ __half g_wq0[QKV_N * XK];          // w_qkv0^T (split fp16), [N][K']
__device__ __half g_wq1[QKV_N * XK];
__device__ __half g_wo0[DIM * XK];            // w_out0^T
__device__ __half g_wo1[DIM * XK];

// ---------------- helpers ----------------------------------------------------
__device__ __forceinline__ uint32_t smem_u32(const void* p) {
    uint32_t a;
    asm("{ .reg .u64 t; cvta.to.shared.u64 t, %1; cvt.u32.u64 %0, t; }"
        : "=r"(a) : "l"(p));
    return a;
}
__device__ __forceinline__ void cp16(uint32_t dst, const void* src) {
    asm volatile("cp.async.cg.shared.global [%0], [%1], 16;"
                 :: "r"(dst), "l"(src));
}
__device__ __forceinline__ void ldsm_x4(uint32_t* r, uint32_t addr) {
    asm volatile("ldmatrix.sync.aligned.m8n8.x4.shared.b16 {%0,%1,%2,%3}, [%4];"
                 : "=r"(r[0]), "=r"(r[1]), "=r"(r[2]), "=r"(r[3]) : "r"(addr));
}
__device__ __forceinline__ void ldsm_x2(uint32_t* r, uint32_t addr) {
    asm volatile("ldmatrix.sync.aligned.m8n8.x2.shared.b16 {%0,%1}, [%2];"
                 : "=r"(r[0]), "=r"(r[1]) : "r"(addr));
}
__device__ __forceinline__ void mma16816(float* c, const uint32_t* a,
                                         const uint32_t* b) {
    asm volatile(
        "mma.sync.aligned.m16n8k16.row.col.f32.f16.f16.f32 "
        "{%0,%1,%2,%3}, {%4,%5,%6,%7}, {%8,%9}, {%0,%1,%2,%3};"
        : "+f"(c[0]), "+f"(c[1]), "+f"(c[2]), "+f"(c[3])
        : "r"(a[0]), "r"(a[1]), "r"(a[2]), "r"(a[3]), "r"(b[0]), "r"(b[1]));
}

// ---------------- conversion: x -> split fp16 -------------------------------
__global__ __launch_bounds__(256) void convert_x_kernel(
    const float* __restrict__ x0, const float* __restrict__ x1)
{
    int idx = blockIdx.x * 256 + threadIdx.x;
    if (idx >= S_TOT * DIM) return;
    int s = idx / DIM, k = idx - s * DIM;
    float v = (s < S0) ? x0[(size_t)s * DIM + k] : x1[(size_t)(s - S0) * DIM + k];
    __half hi = __float2half_rn(v);
    __half lo = __float2half_rn(v - __half2float(hi));
    g_xh[(size_t)s * XK + k] = hi;
    g_xh[(size_t)s * XK + DIM + k] = lo;
}

// ---------------- conversion: weights -> transposed split fp16 --------------
__global__ __launch_bounds__(256) void convert_w_kernel(
    const float* __restrict__ src, int N, int sel)
{
    __shared__ float tile[32][33];
    __half* dst = (sel == 0) ? g_wq0 : (sel == 1) ? g_wq1 : (sel == 2) ? g_wo0 : g_wo1;
    int n0 = blockIdx.x * 32;
    int k0 = blockIdx.y * 32;
    int tx = threadIdx.x, ty = threadIdx.y;   // (32, 8)
#pragma unroll
    for (int i = 0; i < 32; i += 8)
        tile[ty + i][tx] = src[(size_t)(k0 + ty + i) * N + n0 + tx];
    __syncthreads();
#pragma unroll
    for (int i = 0; i < 32; i += 8) {
        int n = n0 + ty + i;
        int k = k0 + tx;
        float v = tile[tx][ty + i];
        __half hi = __float2half_rn(v);
        __half lo = __float2half_rn(v - __half2float(hi));
        dst[(size_t)n * XK + k] = hi;
        dst[(size_t)n * XK + DIM + k] = lo;
    }
}

// ---------------- mma.sync split-fp16 GEMM, 128x128 tile --------------------
// MODE 0: A=g_xh, B=wq by modality; scatter cols (t,h,d) into g_q/g_k/g_v.
// MODE 1: A=g_ah, B=wo by modality; write d_out.
template <int MODE>
__global__ __launch_bounds__(256, 1) void gemm_mma(float* __restrict__ out)
{
    extern __shared__ char sm[];
    const int tid = threadIdx.x;
    const int wid = tid >> 5;
    const int lane = tid & 31;
    const int m0 = blockIdx.y * 128;
    const int n0 = blockIdx.x * 128;

    const __half* A = (MODE == 0) ? g_xh : g_ah;
    const __half* B;
    if (MODE == 0) B = (m0 < S0) ? g_wq0 : g_wq1;
    else           B = (m0 < S0) ? g_wo0 : g_wo1;

    const uint32_t smb = smem_u32(sm);

    // global->smem load coords: 2 threads per row, 4x16B each per tile
    const int lrow  = tid >> 1;
    const int lslot = (tid & 1) * 4;
    const __half* gA = A + (size_t)(m0 + lrow) * XK + lslot * 8;
    const __half* gB = B + (size_t)(n0 + lrow) * XK + lslot * 8;
    const uint32_t sOff = (uint32_t)lrow * (PITCH * 2) + lslot * 16;

    const int wm = wid >> 2;   // 0..1  (M)
    const int wn = wid & 3;    // 0..3  (N)

    // ldmatrix per-lane byte offsets (within a tile)
    const int arow = wm * 64 + (lane & 7) + ((lane >> 3) & 1) * 8;
    const uint32_t aoffs = (uint32_t)arow * (PITCH * 2) + ((lane >> 4) * 8) * 2;
    const int brow = wn * 32 + (lane & 7);
    const uint32_t boffs = (uint32_t)brow * (PITCH * 2) + (((lane >> 3) & 1) * 8) * 2;

    float acc[4][4][4];
#pragma unroll
    for (int i = 0; i < 4; i++)
#pragma unroll
        for (int j = 0; j < 4; j++)
#pragma unroll
            for (int e = 0; e < 4; e++) acc[i][j][e] = 0.0f;

    // ---- prologue: stage 0 ----
    {
        uint32_t d = smb + sOff;
#pragma unroll
        for (int i = 0; i < 4; i++) {
            cp16(d + i * 16,              gA + i * 8);
            cp16(d + TILE_B + i * 16,     gA + DIM + i * 8);
            cp16(d + 2 * TILE_B + i * 16, gB + i * 8);
            cp16(d + 3 * TILE_B + i * 16, gB + DIM + i * 8);
        }
        asm volatile("cp.async.commit_group;" ::: "memory");
    }

#pragma unroll 1
    for (int s = 0; s < N_STAGE; s++) {
        if (s + 1 < N_STAGE) {
            uint32_t d = smb + ((s + 1) & 1) * STAGE_B + sOff;
            const __half* pa = gA + (s + 1) * KCH;
            const __half* pb = gB + (s + 1) * KCH;
#pragma unroll
            for (int i = 0; i < 4; i++) {
                cp16(d + i * 16,              pa + i * 8);
                cp16(d + TILE_B + i * 16,     pa + DIM + i * 8);
                cp16(d + 2 * TILE_B + i * 16, pb + i * 8);
                cp16(d + 3 * TILE_B + i * 16, pb + DIM + i * 8);
            }
            asm volatile("cp.async.commit_group;" ::: "memory");
            asm volatile("cp.async.wait_group 1;" ::: "memory");
        } else {
            asm volatile("cp.async.wait_group 0;" ::: "memory");
        }
        __syncthreads();

        const uint32_t sb = smb + (s & 1) * STAGE_B;
#pragma unroll
        for (int ks = 0; ks < 4; ks++) {
            const uint32_t aA = sb + aoffs + ks * 32;
            const uint32_t aB = sb + 2 * TILE_B + boffs + ks * 32;
            uint32_t ah[4][4], al[4][4], bh[4][2], bl[4][2];
#pragma unroll
            for (int mt = 0; mt < 4; mt++) {
                ldsm_x4(ah[mt], aA + mt * 16 * (PITCH * 2));
                ldsm_x4(al[mt], aA + TILE_B + mt * 16 * (PITCH * 2));
            }
#pragma unroll
            for (int nt = 0; nt < 4; nt++) {
                ldsm_x2(bh[nt], aB + nt * 8 * (PITCH * 2));
                ldsm_x2(bl[nt], aB + TILE_B + nt * 8 * (PITCH * 2));
            }
#pragma unroll
            for (int mt = 0; mt < 4; mt++)
#pragma unroll
                for (int nt = 0; nt < 4; nt++) {
                    mma16816(acc[mt][nt], ah[mt], bh[nt]);
                    mma16816(acc[mt][nt], ah[mt], bl[nt]);
                    mma16816(acc[mt][nt], al[mt], bh[nt]);
                }
        }
        __syncthreads();   // protect buffer (s&1) from next iteration's cp.async
    }

    // ---- epilogue ----
    const int g  = lane >> 2;
    const int tg = lane & 3;
#pragma unroll
    for (int mt = 0; mt < 4; mt++) {
        const int m = m0 + wm * 64 + mt * 16 + g;
#pragma unroll
        for (int nt = 0; nt < 4; nt++) {
            const int col = n0 + wn * 32 + nt * 8 + tg * 2;
            if (MODE == 0) {
                int tsel = col / DIM;
                int rem = col - tsel * DIM;
                int h = rem >> 6;
                int d = rem & 63;
                float* dstb = (tsel == 0 ? g_q : (tsel == 1 ? g_k : g_v));
                float* p0 = dstb + ((size_t)h * S_TOT + m) * HD + d;
                *(float2*)p0            = make_float2(acc[mt][nt][0], acc[mt][nt][1]);
                *(float2*)(p0 + 8 * HD) = make_float2(acc[mt][nt][2], acc[mt][nt][3]);
            } else {
                float* p0 = out + (size_t)m * DIM + col;
                *(float2*)p0             = make_float2(acc[mt][nt][0], acc[mt][nt][1]);
                *(float2*)(p0 + 8 * DIM) = make_float2(acc[mt][nt][2], acc[mt][nt][3]);
            }
        }
    }
}

// ---------------- RMSNorm + RoPE, one warp per (h, s) row -------------------
__global__ __launch_bounds__(256) void norm_rope_kernel(
    const float* __restrict__ gq0, const float* __restrict__ gk0,
    const float* __restrict__ gq1, const float* __restrict__ gk1)
{
    const int warp = (blockIdx.x * blockDim.x + threadIdx.x) >> 5;
    const int lane = threadIdx.x & 31;
    if (warp >= NH * S_TOT) return;
    const int h = warp / S_TOT;
    const int s = warp - h * S_TOT;

    const float* gq;
    const float* gk;
    int pos;
    if (s < S0) { gq = gq0; gk = gk0; pos = s; }
    else        { gq = gq1; gk = gk1; pos = s - S0; }

    const double LN1E4_OVER_32 = 0.2878231217852968;  // ln(10000)/32
    float inv = (float)exp(-(double)lane * LN1E4_OVER_32);
    float f = (float)pos * inv;
    float cs, sn;
    sincosf(f, &sn, &cs);

    const size_t base = ((size_t)h * S_TOT + s) * HD;
    const float gql = gq[lane], gqh = gq[lane + 32];
    const float gkl = gk[lane], gkh = gk[lane + 32];

    {
        float lo = g_q[base + lane];
        float hi = g_q[base + lane + 32];
        float ss = lo * lo + hi * hi;
#pragma unroll
        for (int off = 16; off; off >>= 1)
            ss += __shfl_xor_sync(0xffffffffu, ss, off);
        float r = rsqrtf(ss * (1.0f / 64.0f) + 1e-6f);
        float nl = lo * r * gql;
        float nh = hi * r * gqh;
        g_q[base + lane]      = nl * cs - nh * sn;
        g_q[base + lane + 32] = nh * cs + nl * sn;
    }
    {
        float lo = g_k[base + lane];
        float hi = g_k[base + lane + 32];
        float ss = lo * lo + hi * hi;
#pragma unroll
        for (int off = 16; off; off >>= 1)
            ss += __shfl_xor_sync(0xffffffffu, ss, off);
        float r = rsqrtf(ss * (1.0f / 64.0f) + 1e-6f);
        float nl = lo * r * gkl;
        float nh = hi * r * gkh;
        g_k[base + lane]      = nl * cs - nh * sn;
        g_k[base + lane + 32] = nh * cs + nl * sn;
    }
}

// ---------------- attention: 1 query row per thread, online softmax ---------
__global__ __launch_bounds__(128) void attn_kernel()
{
    const int h = blockIdx.y;
    const int qi = blockIdx.x * 128 + threadIdx.x;

    __shared__ float Ks[32 * 64];
    __shared__ float Vs[32 * 64];

    float q[64];
    {
        const float* qptr = g_q + ((size_t)h * S_TOT + qi) * HD;
#pragma unroll
        for (int i = 0; i < 16; i++) {
            float4 v = *(const float4*)(qptr + i * 4);
            q[i * 4 + 0] = v.x; q[i * 4 + 1] = v.y;
            q[i * 4 + 2] = v.z; q[i * 4 + 3] = v.w;
        }
    }

    float o[64];
#pragma unroll
    for (int i = 0; i < 64; i++) o[i] = 0.0f;
    float m = -1e30f, l = 0.0f;

    const float* kbase = g_k + (size_t)h * S_TOT * HD;
    const float* vbase = g_v + (size_t)h * S_TOT * HD;
    const float scale = 0.125f;

    for (int kt = 0; kt < S_TOT; kt += 32) {
        __syncthreads();
#pragma unroll
        for (int i = 0; i < 4; i++) {
            int off = i * 512 + threadIdx.x * 4;
            *(float4*)&Ks[off] = *(const float4*)(kbase + (size_t)kt * HD + off);
            *(float4*)&Vs[off] = *(const float4*)(vbase + (size_t)kt * HD + off);
        }
        __syncthreads();

#pragma unroll
        for (int half = 0; half < 2; half++) {
            float sv[16];
#pragma unroll
            for (int kk = 0; kk < 16; kk++) {
                const float* kr = &Ks[(half * 16 + kk) * 64];
                float d0 = 0.f, d1 = 0.f, d2 = 0.f, d3 = 0.f;
#pragma unroll
                for (int i = 0; i < 16; i++) {
                    float4 kv = *(const float4*)(kr + i * 4);
                    d0 += q[i * 4 + 0] * kv.x;
                    d1 += q[i * 4 + 1] * kv.y;
                    d2 += q[i * 4 + 2] * kv.z;
                    d3 += q[i * 4 + 3] * kv.w;
                }
                sv[kk] = ((d0 + d1) + (d2 + d3)) * scale;
            }
            float mt = sv[0];
#pragma unroll
            for (int kk = 1; kk < 16; kk++) mt = fmaxf(mt, sv[kk]);
            float mnew = fmaxf(m, mt);
            float corr = __expf(m - mnew);
            m = mnew;
            l *= corr;
#pragma unroll
            for (int i = 0; i < 64; i++) o[i] *= corr;
#pragma unroll
            for (int kk = 0; kk < 16; kk++) {
                float p = __expf(sv[kk] - m);
                l += p;
                const float* vr = &Vs[(half * 16 + kk) * 64];
#pragma unroll
                for (int i = 0; i < 16; i++) {
                    float4 vv = *(const float4*)(vr + i * 4);
                    o[i * 4 + 0] += p * vv.x;
                    o[i * 4 + 1] += p * vv.y;
                    o[i * 4 + 2] += p * vv.z;
                    o[i * 4 + 3] += p * vv.w;
                }
            }
        }
    }

    const float linv = 1.0f / l;
    // write split-fp16 directly into the out-projection A operand
    __half* optr = g_ah + (size_t)qi * XK + h * HD;
#pragma unroll
    for (int i = 0; i < 64; i += 2) {
        float v0 = o[i] * linv, v1 = o[i + 1] * linv;
        __half h0 = __float2half_rn(v0), h1 = __float2half_rn(v1);
        __half l0 = __float2half_rn(v0 - __half2float(h0));
        __half l1 = __float2half_rn(v1 - __half2float(h1));
        *(__half2*)(optr + i)       = __halves2half2(h0, h1);
        *(__half2*)(optr + DIM + i) = __halves2half2(l0, l1);
    }
}

// ---------------- launch ----------------------------------------------------
extern "C" void kernel_launch(void* const* d_in, const int* in_sizes, int n_in,
                              void* d_out, int out_size)
{
    const float* x0     = (const float*)d_in[0];
    const float* x1     = (const float*)d_in[1];
    const float* w_qkv0 = (const float*)d_in[2];
    const float* w_qkv1 = (const float*)d_in[3];
    const float* w_out0 = (const float*)d_in[4];
    const float* w_out1 = (const float*)d_in[5];
    const float* gq0    = (const float*)d_in[6];
    const float* gk0    = (const float*)d_in[7];
    const float* gq1    = (const float*)d_in[8];
    const float* gk1    = (const float*)d_in[9];
    float* out = (float*)d_out;

    cudaFuncSetAttribute(gemm_mma<0>, cudaFuncAttributeMaxDynamicSharedMemorySize, GEMM_SMEM);
    cudaFuncSetAttribute(gemm_mma<1>, cudaFuncAttributeMaxDynamicSharedMemorySize, GEMM_SMEM);

    // 0: fp32 -> split fp16 conversions
    convert_x_kernel<<<(S_TOT * DIM + 255) / 256, 256>>>(x0, x1);
    convert_w_kernel<<<dim3(QKV_N / 32, DIM / 32), dim3(32, 8)>>>(w_qkv0, QKV_N, 0);
    convert_w_kernel<<<dim3(QKV_N / 32, DIM / 32), dim3(32, 8)>>>(w_qkv1, QKV_N, 1);
    convert_w_kernel<<<dim3(DIM / 32,   DIM / 32), dim3(32, 8)>>>(w_out0, DIM, 2);
    convert_w_kernel<<<dim3(DIM / 32,   DIM / 32), dim3(32, 8)>>>(w_out1, DIM, 3);

    // A: QKV projection on tensor cores (mma.sync) + scatter into q/k/v
    gemm_mma<0><<<dim3(QKV_N / 128, S_TOT / 128), 256, GEMM_SMEM>>>(nullptr);

    // B: RMSNorm + RoPE
    {
        int warps = NH * S_TOT;
        norm_rope_kernel<<<(warps * 32 + 255) / 256, 256>>>(gq0, gk0, gq1, gk1);
    }

    // C: attention (fp32 SIMT, emits split-fp16 A for out-proj)
    attn_kernel<<<dim3(S_TOT / 128, NH), 128>>>();

    // D: output projection on tensor cores
    gemm_mma<1><<<dim3(DIM / 128, S_TOT / 128), 256, GEMM_SMEM>>>(out);
}

// round 8
// speedup vs baseline: 2.6075x; 2.0583x over previous
#include <cuda_runtime.h>
#include <cuda_fp16.h>
#include <math.h>
#include <stdint.h>

#define S_TOT 2304
#define S0    2048
#define DIM   1536
#define NH    24
#define HD    64
#define QKV_N 4608
#define XK    3072          // split-fp16 K layout: [hi 0:1536 | lo 1536:3072]

// GEMM staging
#define N_STAGE 24
#define KCH     64                  // halves per stage
#define PITCH   72                  // halves per smem row (pad 8)
#define TILE_B  (128 * PITCH * 2)   // 18432 B per operand tile
#define STAGE_B (4 * TILE_B)        // Ah, Al, Bh, Bl
#define GEMM_SMEM (2 * STAGE_B)     // 147456 B double-buffered

// Attention staging
#define BQ 128
#define BK 64
#define AP_B 272                    // bytes per K/V smem row (128 halves + 8 pad)
#define KV_TILE_B (64 * AP_B)       // 17408
#define STAGE2_B (2 * KV_TILE_B)    // K + V per stage = 34816
#define ATT_SMEM (2 * STAGE2_B)     // 69632 double-buffered
#define N_KT (S_TOT / BK)           // 36

// ---------------- scratch (device globals; no allocation allowed) -----------
__device__ float  g_q[NH * S_TOT * HD];       // fp32 q (pre-norm)
__device__ float  g_k[NH * S_TOT * HD];       // fp32 k (pre-norm)
__device__ __half g_qs[NH * S_TOT * 128];     // q split fp16 [hi 64 | lo 64], pre-scaled
__device__ __half g_ks[NH * S_TOT * 128];     // k split fp16
__device__ __half g_vs[NH * S_TOT * 128];     // v split fp16
__device__ __half g_xh [S_TOT * XK];          // x (split fp16), K-major
__device__ __half g_ah [S_TOT * XK];          // attention out (split fp16)
__device__ __half g_wq0[QKV_N * XK];          // w_qkv0^T (split fp16), [N][K']
__device__ __half g_wq1[QKV_N * XK];
__device__ __half g_wo0[DIM * XK];            // w_out0^T
__device__ __half g_wo1[DIM * XK];

// ---------------- helpers ----------------------------------------------------
__device__ __forceinline__ uint32_t smem_u32(const void* p) {
    uint32_t a;
    asm("{ .reg .u64 t; cvta.to.shared.u64 t, %1; cvt.u32.u64 %0, t; }"
        : "=r"(a) : "l"(p));
    return a;
}
__device__ __forceinline__ void cp16(uint32_t dst, const void* src) {
    asm volatile("cp.async.cg.shared.global [%0], [%1], 16;"
                 :: "r"(dst), "l"(src));
}
__device__ __forceinline__ void ldsm_x4(uint32_t* r, uint32_t addr) {
    asm volatile("ldmatrix.sync.aligned.m8n8.x4.shared.b16 {%0,%1,%2,%3}, [%4];"
                 : "=r"(r[0]), "=r"(r[1]), "=r"(r[2]), "=r"(r[3]) : "r"(addr));
}
__device__ __forceinline__ void ldsm_x4_t(uint32_t* r, uint32_t addr) {
    asm volatile("ldmatrix.sync.aligned.m8n8.x4.trans.shared.b16 {%0,%1,%2,%3}, [%4];"
                 : "=r"(r[0]), "=r"(r[1]), "=r"(r[2]), "=r"(r[3]) : "r"(addr));
}
__device__ __forceinline__ void ldsm_x2(uint32_t* r, uint32_t addr) {
    asm volatile("ldmatrix.sync.aligned.m8n8.x2.shared.b16 {%0,%1}, [%2];"
                 : "=r"(r[0]), "=r"(r[1]) : "r"(addr));
}
__device__ __forceinline__ void mma16816(float* c, const uint32_t* a,
                                         const uint32_t* b) {
    asm volatile(
        "mma.sync.aligned.m16n8k16.row.col.f32.f16.f16.f32 "
        "{%0,%1,%2,%3}, {%4,%5,%6,%7}, {%8,%9}, {%0,%1,%2,%3};"
        : "+f"(c[0]), "+f"(c[1]), "+f"(c[2]), "+f"(c[3])
        : "r"(a[0]), "r"(a[1]), "r"(a[2]), "r"(a[3]), "r"(b[0]), "r"(b[1]));
}

// ---------------- conversion: x -> split fp16 -------------------------------
__global__ __launch_bounds__(256) void convert_x_kernel(
    const float* __restrict__ x0, const float* __restrict__ x1)
{
    int idx = blockIdx.x * 256 + threadIdx.x;
    if (idx >= S_TOT * DIM) return;
    int s = idx / DIM, k = idx - s * DIM;
    float v = (s < S0) ? x0[(size_t)s * DIM + k] : x1[(size_t)(s - S0) * DIM + k];
    __half hi = __float2half_rn(v);
    __half lo = __float2half_rn(v - __half2float(hi));
    g_xh[(size_t)s * XK + k] = hi;
    g_xh[(size_t)s * XK + DIM + k] = lo;
}

// ---------------- conversion: weights -> transposed split fp16 --------------
__global__ __launch_bounds__(256) void convert_w_kernel(
    const float* __restrict__ src, int N, int sel)
{
    __shared__ float tile[32][33];
    __half* dst = (sel == 0) ? g_wq0 : (sel == 1) ? g_wq1 : (sel == 2) ? g_wo0 : g_wo1;
    int n0 = blockIdx.x * 32;
    int k0 = blockIdx.y * 32;
    int tx = threadIdx.x, ty = threadIdx.y;   // (32, 8)
#pragma unroll
    for (int i = 0; i < 32; i += 8)
        tile[ty + i][tx] = src[(size_t)(k0 + ty + i) * N + n0 + tx];
    __syncthreads();
#pragma unroll
    for (int i = 0; i < 32; i += 8) {
        int n = n0 + ty + i;
        int k = k0 + tx;
        float v = tile[tx][ty + i];
        __half hi = __float2half_rn(v);
        __half lo = __float2half_rn(v - __half2float(hi));
        dst[(size_t)n * XK + k] = hi;
        dst[(size_t)n * XK + DIM + k] = lo;
    }
}

// ---------------- mma.sync split-fp16 GEMM, 128x128 tile --------------------
// MODE 0: A=g_xh, B=wq by modality; q,k -> fp32 g_q/g_k, v -> split-fp16 g_vs.
// MODE 1: A=g_ah, B=wo by modality; write d_out.
template <int MODE>
__global__ __launch_bounds__(256, 1) void gemm_mma(float* __restrict__ out)
{
    extern __shared__ char sm[];
    const int tid = threadIdx.x;
    const int wid = tid >> 5;
    const int lane = tid & 31;
    const int m0 = blockIdx.y * 128;
    const int n0 = blockIdx.x * 128;

    const __half* A = (MODE == 0) ? g_xh : g_ah;
    const __half* B;
    if (MODE == 0) B = (m0 < S0) ? g_wq0 : g_wq1;
    else           B = (m0 < S0) ? g_wo0 : g_wo1;

    const uint32_t smb = smem_u32(sm);

    const int lrow  = tid >> 1;
    const int lslot = (tid & 1) * 4;
    const __half* gA = A + (size_t)(m0 + lrow) * XK + lslot * 8;
    const __half* gB = B + (size_t)(n0 + lrow) * XK + lslot * 8;
    const uint32_t sOff = (uint32_t)lrow * (PITCH * 2) + lslot * 16;

    const int wm = wid >> 2;
    const int wn = wid & 3;

    const int arow = wm * 64 + (lane & 15);
    const uint32_t aoffs = (uint32_t)arow * (PITCH * 2) + (lane >> 4) * 16;
    const int brow = wn * 32 + (lane & 7);
    const uint32_t boffs = (uint32_t)brow * (PITCH * 2) + ((lane >> 3) & 1) * 16;

    float acc[4][4][4];
#pragma unroll
    for (int i = 0; i < 4; i++)
#pragma unroll
        for (int j = 0; j < 4; j++)
#pragma unroll
            for (int e = 0; e < 4; e++) acc[i][j][e] = 0.0f;

    {
        uint32_t d = smb + sOff;
#pragma unroll
        for (int i = 0; i < 4; i++) {
            cp16(d + i * 16,              gA + i * 8);
            cp16(d + TILE_B + i * 16,     gA + DIM + i * 8);
            cp16(d + 2 * TILE_B + i * 16, gB + i * 8);
            cp16(d + 3 * TILE_B + i * 16, gB + DIM + i * 8);
        }
        asm volatile("cp.async.commit_group;" ::: "memory");
    }

#pragma unroll 1
    for (int s = 0; s < N_STAGE; s++) {
        if (s + 1 < N_STAGE) {
            uint32_t d = smb + ((s + 1) & 1) * STAGE_B + sOff;
            const __half* pa = gA + (s + 1) * KCH;
            const __half* pb = gB + (s + 1) * KCH;
#pragma unroll
            for (int i = 0; i < 4; i++) {
                cp16(d + i * 16,              pa + i * 8);
                cp16(d + TILE_B + i * 16,     pa + DIM + i * 8);
                cp16(d + 2 * TILE_B + i * 16, pb + i * 8);
                cp16(d + 3 * TILE_B + i * 16, pb + DIM + i * 8);
            }
            asm volatile("cp.async.commit_group;" ::: "memory");
            asm volatile("cp.async.wait_group 1;" ::: "memory");
        } else {
            asm volatile("cp.async.wait_group 0;" ::: "memory");
        }
        __syncthreads();

        const uint32_t sb = smb + (s & 1) * STAGE_B;
#pragma unroll
        for (int ks = 0; ks < 4; ks++) {
            const uint32_t aA = sb + aoffs + ks * 32;
            const uint32_t aB = sb + 2 * TILE_B + boffs + ks * 32;
            uint32_t ah[4][4], al[4][4], bh[4][2], bl[4][2];
#pragma unroll
            for (int mt = 0; mt < 4; mt++) {
                ldsm_x4(ah[mt], aA + mt * 16 * (PITCH * 2));
                ldsm_x4(al[mt], aA + TILE_B + mt * 16 * (PITCH * 2));
            }
#pragma unroll
            for (int nt = 0; nt < 4; nt++) {
                ldsm_x2(bh[nt], aB + nt * 8 * (PITCH * 2));
                ldsm_x2(bl[nt], aB + TILE_B + nt * 8 * (PITCH * 2));
            }
#pragma unroll
            for (int mt = 0; mt < 4; mt++)
#pragma unroll
                for (int nt = 0; nt < 4; nt++) {
                    mma16816(acc[mt][nt], ah[mt], bh[nt]);
                    mma16816(acc[mt][nt], ah[mt], bl[nt]);
                    mma16816(acc[mt][nt], al[mt], bh[nt]);
                }
        }
        __syncthreads();
    }

    // ---- epilogue ----
    const int g  = lane >> 2;
    const int tg = lane & 3;
#pragma unroll
    for (int mt = 0; mt < 4; mt++) {
        const int m = m0 + wm * 64 + mt * 16 + g;
#pragma unroll
        for (int nt = 0; nt < 4; nt++) {
            const int col = n0 + wn * 32 + nt * 8 + tg * 2;
            if (MODE == 0) {
                int tsel = col / DIM;
                int rem = col - tsel * DIM;
                int h = rem >> 6;
                int d = rem & 63;
                if (tsel < 2) {
                    float* dstb = (tsel == 0 ? g_q : g_k);
                    float* p0 = dstb + ((size_t)h * S_TOT + m) * HD + d;
                    *(float2*)p0            = make_float2(acc[mt][nt][0], acc[mt][nt][1]);
                    *(float2*)(p0 + 8 * HD) = make_float2(acc[mt][nt][2], acc[mt][nt][3]);
                } else {
                    // v -> split fp16 [hi 0:64 | lo 64:128]
                    __half* vb = g_vs + ((size_t)h * S_TOT + m) * 128 + d;
#pragma unroll
                    for (int rr = 0; rr < 2; rr++) {
                        float a0 = acc[mt][nt][rr * 2 + 0];
                        float a1 = acc[mt][nt][rr * 2 + 1];
                        __half2 hp = __floats2half2_rn(a0, a1);
                        float2 hf = __half22float2(hp);
                        __half2 lp = __floats2half2_rn(a0 - hf.x, a1 - hf.y);
                        __half* p = vb + (size_t)rr * 8 * 128;
                        *(__half2*)p        = hp;
                        *(__half2*)(p + 64) = lp;
                    }
                }
            } else {
                float* p0 = out + (size_t)m * DIM + col;
                *(float2*)p0             = make_float2(acc[mt][nt][0], acc[mt][nt][1]);
                *(float2*)(p0 + 8 * DIM) = make_float2(acc[mt][nt][2], acc[mt][nt][3]);
            }
        }
    }
}

// ---------------- RMSNorm + RoPE -> split fp16 q (pre-scaled) / k -----------
__global__ __launch_bounds__(256) void norm_rope_kernel(
    const float* __restrict__ gq0, const float* __restrict__ gk0,
    const float* __restrict__ gq1, const float* __restrict__ gk1)
{
    const int warp = (blockIdx.x * blockDim.x + threadIdx.x) >> 5;
    const int lane = threadIdx.x & 31;
    if (warp >= NH * S_TOT) return;
    const int h = warp / S_TOT;
    const int s = warp - h * S_TOT;

    const float* gq;
    const float* gk;
    int pos;
    if (s < S0) { gq = gq0; gk = gk0; pos = s; }
    else        { gq = gq1; gk = gk1; pos = s - S0; }

    const double LN1E4_OVER_32 = 0.2878231217852968;  // ln(10000)/32
    float inv = (float)exp(-(double)lane * LN1E4_OVER_32);
    float f = (float)pos * inv;
    float cs, sn;
    sincosf(f, &sn, &cs);

    const size_t base   = ((size_t)h * S_TOT + s) * HD;
    const size_t base2  = ((size_t)h * S_TOT + s) * 128;
    const float gql = gq[lane], gqh = gq[lane + 32];
    const float gkl = gk[lane], gkh = gk[lane + 32];

    {
        float lo = g_q[base + lane];
        float hi = g_q[base + lane + 32];
        float ss = lo * lo + hi * hi;
#pragma unroll
        for (int off = 16; off; off >>= 1)
            ss += __shfl_xor_sync(0xffffffffu, ss, off);
        float r = rsqrtf(ss * (1.0f / 64.0f) + 1e-6f);
        float nl = lo * r * gql;
        float nh = hi * r * gqh;
        float q0 = (nl * cs - nh * sn) * 0.125f;   // fold 1/sqrt(D)
        float q1 = (nh * cs + nl * sn) * 0.125f;
        __half h0 = __float2half_rn(q0), h1 = __float2half_rn(q1);
        g_qs[base2 + lane]       = h0;
        g_qs[base2 + lane + 32]  = h1;
        g_qs[base2 + 64 + lane]      = __float2half_rn(q0 - __half2float(h0));
        g_qs[base2 + 96 + lane]      = __float2half_rn(q1 - __half2float(h1));
    }
    {
        float lo = g_k[base + lane];
        float hi = g_k[base + lane + 32];
        float ss = lo * lo + hi * hi;
#pragma unroll
        for (int off = 16; off; off >>= 1)
            ss += __shfl_xor_sync(0xffffffffu, ss, off);
        float r = rsqrtf(ss * (1.0f / 64.0f) + 1e-6f);
        float nl = lo * r * gkl;
        float nh = hi * r * gkh;
        float k0 = nl * cs - nh * sn;
        float k1 = nh * cs + nl * sn;
        __half h0 = __float2half_rn(k0), h1 = __float2half_rn(k1);
        g_ks[base2 + lane]       = h0;
        g_ks[base2 + lane + 32]  = h1;
        g_ks[base2 + 64 + lane]      = __float2half_rn(k0 - __half2float(h0));
        g_ks[base2 + 96 + lane]      = __float2half_rn(k1 - __half2float(h1));
    }
}

// ---------------- flash attention on mma.sync, split fp16 -------------------
// CTA: 128 queries x 1 head, 8 warps (16 q-rows each). K-tiles of 64 keys.
__global__ __launch_bounds__(256, 1) void attn_mma_kernel()
{
    extern __shared__ char sm[];
    const uint32_t smb = smem_u32(sm);
    const int tid = threadIdx.x;
    const int wq = tid >> 5;
    const int lane = tid & 31;
    const int h = blockIdx.y;
    const int q0 = blockIdx.x * BQ;

    const __half* Qg = g_qs + ((size_t)h * S_TOT + q0) * 128;
    const __half* Kg = g_ks + (size_t)h * S_TOT * 128;
    const __half* Vg = g_vs + (size_t)h * S_TOT * 128;

    // ---- Q tile -> smem (stage-0 area) -> register fragments ----
    {
        int rid = tid >> 1;
        int hb = (tid & 1) * 128;
        const char* src = (const char*)(Qg + (size_t)rid * 128) + hb;
        uint32_t dst = smb + (uint32_t)rid * AP_B + hb;
#pragma unroll
        for (int i = 0; i < 8; i++) cp16(dst + i * 16, src + i * 16);
        asm volatile("cp.async.commit_group;" ::: "memory");
        asm volatile("cp.async.wait_group 0;" ::: "memory");
    }
    __syncthreads();

    uint32_t qh[4][4], ql[4][4];
    {
        uint32_t base = smb + (uint32_t)(wq * 16 + (lane & 15)) * AP_B
                      + (lane >> 4) * 16;
#pragma unroll
        for (int c = 0; c < 4; c++) {
            ldsm_x4(qh[c], base + c * 32);
            ldsm_x4(ql[c], base + 128 + c * 32);
        }
    }
    __syncthreads();

    // cp.async coords for K/V tiles: 4 threads per 256B row
    const int rid4 = tid >> 2;
    const int slot = (tid & 3) * 64;

    // ldmatrix per-lane offsets
    const int grp = lane >> 3, lr = lane & 7;
    // K (non-trans): rows = keys, advance jp along rows, c along cols
    const uint32_t k_off = (uint32_t)((grp >> 1) * 8 + lr) * AP_B + (grp & 1) * 16;
    // V (trans): rows = keys (chunk c), advance jp along d cols
    const uint32_t v_off = (uint32_t)((grp & 1) * 8 + lr) * AP_B + (grp >> 1) * 16;

    float o[8][4];
#pragma unroll
    for (int j = 0; j < 8; j++)
#pragma unroll
        for (int e = 0; e < 4; e++) o[j][e] = 0.0f;
    float m0 = -1e30f, m8 = -1e30f, l0 = 0.0f, l8 = 0.0f;

    // prefetch tile 0 into stage 0
    {
        const char* ks = (const char*)(Kg + (size_t)rid4 * 128) + slot;
        const char* vs = (const char*)(Vg + (size_t)rid4 * 128) + slot;
        uint32_t kd = smb + (uint32_t)rid4 * AP_B + slot;
#pragma unroll
        for (int i = 0; i < 4; i++) {
            cp16(kd + i * 16,             ks + i * 16);
            cp16(kd + KV_TILE_B + i * 16, vs + i * 16);
        }
        asm volatile("cp.async.commit_group;" ::: "memory");
    }

#pragma unroll 1
    for (int it = 0; it < N_KT; it++) {
        if (it + 1 < N_KT) {
            const size_t krow = (size_t)((it + 1) * BK + rid4) * 128;
            const char* ks = (const char*)(Kg + krow) + slot;
            const char* vs = (const char*)(Vg + krow) + slot;
            uint32_t kd = smb + ((it + 1) & 1) * STAGE2_B + (uint32_t)rid4 * AP_B + slot;
#pragma unroll
            for (int i = 0; i < 4; i++) {
                cp16(kd + i * 16,             ks + i * 16);
                cp16(kd + KV_TILE_B + i * 16, vs + i * 16);
            }
            asm volatile("cp.async.commit_group;" ::: "memory");
            asm volatile("cp.async.wait_group 1;" ::: "memory");
        } else {
            asm volatile("cp.async.wait_group 0;" ::: "memory");
        }
        __syncthreads();

        const uint32_t kb = smb + (it & 1) * STAGE2_B;
        const uint32_t vb = kb + KV_TILE_B;

        // ---- scores: S = Q K^T (3 split passes), fp32 accum ----
        float sc[8][4];
#pragma unroll
        for (int j = 0; j < 8; j++)
#pragma unroll
            for (int e = 0; e < 4; e++) sc[j][e] = 0.0f;

#pragma unroll
        for (int c = 0; c < 4; c++) {
            uint32_t kf[8][2], kl[8][2];
#pragma unroll
            for (int jp = 0; jp < 4; jp++) {
                uint32_t r[4];
                uint32_t a = kb + k_off + (uint32_t)jp * 16 * AP_B + c * 32;
                ldsm_x4(r, a);
                kf[2 * jp][0] = r[0]; kf[2 * jp][1] = r[1];
                kf[2 * jp + 1][0] = r[2]; kf[2 * jp + 1][1] = r[3];
                ldsm_x4(r, a + 128);
                kl[2 * jp][0] = r[0]; kl[2 * jp][1] = r[1];
                kl[2 * jp + 1][0] = r[2]; kl[2 * jp + 1][1] = r[3];
            }
#pragma unroll
            for (int j = 0; j < 8; j++) {
                mma16816(sc[j], qh[c], kf[j]);
                mma16816(sc[j], qh[c], kl[j]);
                mma16816(sc[j], ql[c], kf[j]);
            }
        }

        // ---- online softmax on fragments ----
        float mx0 = sc[0][0], mx8 = sc[0][2];
#pragma unroll
        for (int j = 0; j < 8; j++) {
            mx0 = fmaxf(mx0, fmaxf(sc[j][0], sc[j][1]));
            mx8 = fmaxf(mx8, fmaxf(sc[j][2], sc[j][3]));
        }
        mx0 = fmaxf(mx0, __shfl_xor_sync(0xffffffffu, mx0, 1));
        mx0 = fmaxf(mx0, __shfl_xor_sync(0xffffffffu, mx0, 2));
        mx8 = fmaxf(mx8, __shfl_xor_sync(0xffffffffu, mx8, 1));
        mx8 = fmaxf(mx8, __shfl_xor_sync(0xffffffffu, mx8, 2));
        float mn0 = fmaxf(m0, mx0), mn8 = fmaxf(m8, mx8);
        float cr0 = __expf(m0 - mn0), cr8 = __expf(m8 - mn8);
        m0 = mn0; m8 = mn8;
        l0 *= cr0; l8 *= cr8;

        uint32_t pha[8], phb[8], pla[8], plb[8];
#pragma unroll
        for (int j = 0; j < 8; j++) {
            float p0 = __expf(sc[j][0] - m0);
            float p1 = __expf(sc[j][1] - m0);
            float p2 = __expf(sc[j][2] - m8);
            float p3 = __expf(sc[j][3] - m8);
            l0 += p0 + p1; l8 += p2 + p3;
            __half2 ha = __floats2half2_rn(p0, p1);
            float2 fa = __half22float2(ha);
            __half2 la = __floats2half2_rn(p0 - fa.x, p1 - fa.y);
            __half2 hb = __floats2half2_rn(p2, p3);
            float2 fb = __half22float2(hb);
            __half2 lb = __floats2half2_rn(p2 - fb.x, p3 - fb.y);
            pha[j] = *(uint32_t*)&ha; pla[j] = *(uint32_t*)&la;
            phb[j] = *(uint32_t*)&hb; plb[j] = *(uint32_t*)&lb;
        }
#pragma unroll
        for (int j = 0; j < 8; j++) {
            o[j][0] *= cr0; o[j][1] *= cr0;
            o[j][2] *= cr8; o[j][3] *= cr8;
        }

        // ---- O += P V (3 split passes) ----
#pragma unroll
        for (int c = 0; c < 4; c++) {
            uint32_t a_h[4] = {pha[2 * c], phb[2 * c], pha[2 * c + 1], phb[2 * c + 1]};
            uint32_t a_l[4] = {pla[2 * c], plb[2 * c], pla[2 * c + 1], plb[2 * c + 1]};
            uint32_t vh[8][2], vl[8][2];
#pragma unroll
            for (int jp = 0; jp < 4; jp++) {
                uint32_t r[4];
                uint32_t a = vb + v_off + (uint32_t)c * 16 * AP_B + jp * 32;
                ldsm_x4_t(r, a);
                vh[2 * jp][0] = r[0]; vh[2 * jp][1] = r[1];
                vh[2 * jp + 1][0] = r[2]; vh[2 * jp + 1][1] = r[3];
                ldsm_x4_t(r, a + 128);
                vl[2 * jp][0] = r[0]; vl[2 * jp][1] = r[1];
                vl[2 * jp + 1][0] = r[2]; vl[2 * jp + 1][1] = r[3];
            }
#pragma unroll
            for (int j = 0; j < 8; j++) {
                mma16816(o[j], a_h, vh[j]);
                mma16816(o[j], a_h, vl[j]);
                mma16816(o[j], a_l, vh[j]);
            }
        }
        __syncthreads();
    }

    // ---- finalize: divide by l, write split fp16 into g_ah ----
    l0 += __shfl_xor_sync(0xffffffffu, l0, 1);
    l0 += __shfl_xor_sync(0xffffffffu, l0, 2);
    l8 += __shfl_xor_sync(0xffffffffu, l8, 1);
    l8 += __shfl_xor_sync(0xffffffffu, l8, 2);
    const float iv0 = 1.0f / l0, iv8 = 1.0f / l8;

    const int g = lane >> 2, tg = lane & 3;
    const int r0 = q0 + wq * 16 + g;
    __half* out0 = g_ah + (size_t)r0 * XK + h * HD + tg * 2;
    __half* out8 = out0 + (size_t)8 * XK;
#pragma unroll
    for (int j = 0; j < 8; j++) {
        float a0 = o[j][0] * iv0, a1 = o[j][1] * iv0;
        __half2 hp = __floats2half2_rn(a0, a1);
        float2 hf = __half22float2(hp);
        __half2 lp = __floats2half2_rn(a0 - hf.x, a1 - hf.y);
        *(__half2*)(out0 + 8 * j)       = hp;
        *(__half2*)(out0 + 8 * j + DIM) = lp;
        float b0 = o[j][2] * iv8, b1 = o[j][3] * iv8;
        hp = __floats2half2_rn(b0, b1);
        hf = __half22float2(hp);
        lp = __floats2half2_rn(b0 - hf.x, b1 - hf.y);
        *(__half2*)(out8 + 8 * j)       = hp;
        *(__half2*)(out8 + 8 * j + DIM) = lp;
    }
}

// ---------------- launch ----------------------------------------------------
extern "C" void kernel_launch(void* const* d_in, const int* in_sizes, int n_in,
                              void* d_out, int out_size)
{
    const float* x0     = (const float*)d_in[0];
    const float* x1     = (const float*)d_in[1];
    const float* w_qkv0 = (const float*)d_in[2];
    const float* w_qkv1 = (const float*)d_in[3];
    const float* w_out0 = (const float*)d_in[4];
    const float* w_out1 = (const float*)d_in[5];
    const float* gq0    = (const float*)d_in[6];
    const float* gk0    = (const float*)d_in[7];
    const float* gq1    = (const float*)d_in[8];
    const float* gk1    = (const float*)d_in[9];
    float* out = (float*)d_out;

    cudaFuncSetAttribute(gemm_mma<0>, cudaFuncAttributeMaxDynamicSharedMemorySize, GEMM_SMEM);
    cudaFuncSetAttribute(gemm_mma<1>, cudaFuncAttributeMaxDynamicSharedMemorySize, GEMM_SMEM);
    cudaFuncSetAttribute(attn_mma_kernel, cudaFuncAttributeMaxDynamicSharedMemorySize, ATT_SMEM);

    // 0: fp32 -> split fp16 conversions
    convert_x_kernel<<<(S_TOT * DIM + 255) / 256, 256>>>(x0, x1);
    convert_w_kernel<<<dim3(QKV_N / 32, DIM / 32), dim3(32, 8)>>>(w_qkv0, QKV_N, 0);
    convert_w_kernel<<<dim3(QKV_N / 32, DIM / 32), dim3(32, 8)>>>(w_qkv1, QKV_N, 1);
    convert_w_kernel<<<dim3(DIM / 32,   DIM / 32), dim3(32, 8)>>>(w_out0, DIM, 2);
    convert_w_kernel<<<dim3(DIM / 32,   DIM / 32), dim3(32, 8)>>>(w_out1, DIM, 3);

    // A: QKV projection (tensor cores) -> q,k fp32; v split fp16
    gemm_mma<0><<<dim3(QKV_N / 128, S_TOT / 128), 256, GEMM_SMEM>>>(nullptr);

    // B: RMSNorm + RoPE -> split fp16 q (pre-scaled), k
    {
        int warps = NH * S_TOT;
        norm_rope_kernel<<<(warps * 32 + 255) / 256, 256>>>(gq0, gk0, gq1, gk1);
    }

    // C: flash attention on tensor cores -> split fp16 g_ah
    attn_mma_kernel<<<dim3(S_TOT / BQ, NH), 256, ATT_SMEM>>>();

    // D: output projection (tensor cores)
    gemm_mma<1><<<dim3(DIM / 128, S_TOT / 128), 256, GEMM_SMEM>>>(out);
}